// round 2
// baseline (speedup 1.0000x reference)
#include <cuda_runtime.h>
#include <math.h>

// ---------------- scratch (device globals; no allocation allowed) -----------
__device__ float g_G[32 * 512 * 512];    // per-batch Gram matrices
__device__ float g_Y[32 * 8192];         // pooled sketch accumulators
__device__ int   g_h1[512], g_h2[512];
__device__ float g_s1[512], g_s2[512];

#define INPUT_DIM 512
#define PROJ_DIM  8192
#define HW        196
#define BATCH     32

// ---------------- kernel A: extract count-sketch (h, s) from dense M --------
// one warp per row of M [512, 8192]; exactly one nonzero per row
__global__ void extract_kernel(const float* __restrict__ M, int* __restrict__ h,
                               float* __restrict__ s) {
    int row  = blockIdx.x * blockDim.y + threadIdx.y;
    int lane = threadIdx.x;
    if (row >= INPUT_DIM) return;
    const float* r = M + (size_t)row * PROJ_DIM;
    for (int j = lane; j < PROJ_DIM; j += 32) {
        float v = r[j];
        if (v != 0.0f) { h[row] = j; s[row] = v; }
    }
}

// ---------------- kernel B: batched Gram G[b] = X_b^T X_b --------------------
// x: [32, 196, 512]; block computes a 64x64 tile of G[b]; 256 threads, 4x4/thread
#define TILE 64
#define KB   16
__global__ void gram_kernel(const float* __restrict__ x) {
    int b  = blockIdx.z;
    int tm = blockIdx.y;   // c1 tile
    int tn = blockIdx.x;   // c2 tile

    __shared__ float As[KB][TILE];
    __shared__ float Bs[KB][TILE];

    const float* xb = x + (size_t)b * HW * INPUT_DIM;
    int tx = threadIdx.x, ty = threadIdx.y;
    int tid = ty * 16 + tx;

    float acc[4][4];
#pragma unroll
    for (int i = 0; i < 4; i++)
#pragma unroll
        for (int j = 0; j < 4; j++) acc[i][j] = 0.0f;

    for (int k0 = 0; k0 < HW; k0 += KB) {
#pragma unroll
        for (int l = 0; l < 4; l++) {
            int idx = tid + l * 256;
            int kk = idx >> 6, cc = idx & 63;
            int k  = k0 + kk;
            float a = 0.0f, bb = 0.0f;
            if (k < HW) {
                a  = xb[(size_t)k * INPUT_DIM + tm * TILE + cc];
                bb = xb[(size_t)k * INPUT_DIM + tn * TILE + cc];
            }
            As[kk][cc] = a;
            Bs[kk][cc] = bb;
        }
        __syncthreads();

#pragma unroll
        for (int kk = 0; kk < KB; kk++) {
            float4 av = *reinterpret_cast<const float4*>(&As[kk][ty * 4]);
            float4 bv = *reinterpret_cast<const float4*>(&Bs[kk][tx * 4]);
            float a[4] = {av.x, av.y, av.z, av.w};
            float bb[4] = {bv.x, bv.y, bv.z, bv.w};
#pragma unroll
            for (int i = 0; i < 4; i++)
#pragma unroll
                for (int j = 0; j < 4; j++) acc[i][j] = fmaf(a[i], bb[j], acc[i][j]);
        }
        __syncthreads();
    }

    float* Gb = g_G + (size_t)b * INPUT_DIM * INPUT_DIM;
#pragma unroll
    for (int i = 0; i < 4; i++) {
        int c1 = tm * TILE + ty * 4 + i;
        float4 v = make_float4(acc[i][0], acc[i][1], acc[i][2], acc[i][3]);
        *reinterpret_cast<float4*>(&Gb[(size_t)c1 * INPUT_DIM + tn * TILE + tx * 4]) = v;
    }
}

// ---------------- kernel Z: zero Y ------------------------------------------
__global__ void zero_kernel() {
    int i = blockIdx.x * blockDim.x + threadIdx.x;
    if (i < BATCH * PROJ_DIM) g_Y[i] = 0.0f;
}

// ---------------- kernel C: scatter Gram into circular-conv bins -------------
// grid: (8 c1-chunks, 32 batches); smem 8192-bin histogram per block
__global__ void scatter_kernel() {
    __shared__ float acc[PROJ_DIM];
    __shared__ int   sh2[INPUT_DIM];
    __shared__ float ss2[INPUT_DIM];

    int b     = blockIdx.y;
    int chunk = blockIdx.x;          // 0..7, 64 c1 each
    int tid   = threadIdx.x;         // 256 threads

    for (int i = tid; i < PROJ_DIM; i += 256) acc[i] = 0.0f;
    for (int i = tid; i < INPUT_DIM; i += 256) { sh2[i] = g_h2[i]; ss2[i] = g_s2[i]; }
    __syncthreads();

    const float* Gb = g_G + (size_t)b * INPUT_DIM * INPUT_DIM;
    for (int c1i = 0; c1i < 64; c1i++) {
        int c1 = chunk * 64 + c1i;
        int   h1 = g_h1[c1];
        float s1 = g_s1[c1];
        const float* row = Gb + (size_t)c1 * INPUT_DIM;
        for (int c2 = tid; c2 < INPUT_DIM; c2 += 256) {
            float v = row[c2] * s1 * ss2[c2];
            int k = (h1 + sh2[c2]) & (PROJ_DIM - 1);
            atomicAdd(&acc[k], v);
        }
    }
    __syncthreads();

    float* Yb = g_Y + (size_t)b * PROJ_DIM;
    for (int i = tid; i < PROJ_DIM; i += 256) atomicAdd(&Yb[i], acc[i]);
}

// ---------------- kernel D: signed sqrt + L2 normalize -----------------------
// note: y = sign(v)*sqrt(|v|) so y^2 = |v|; norm^2 = sum |v|
__global__ void finalize_kernel(float* __restrict__ out) {
    __shared__ float red[256];
    int b   = blockIdx.x;
    int tid = threadIdx.x;
    const float* Yb = g_Y + (size_t)b * PROJ_DIM;

    float sum = 0.0f;
    for (int i = tid; i < PROJ_DIM; i += 256) sum += fabsf(Yb[i]);
    red[tid] = sum;
    __syncthreads();
    for (int off = 128; off > 0; off >>= 1) {
        if (tid < off) red[tid] += red[tid + off];
        __syncthreads();
    }
    float inv = rsqrtf(fmaxf(red[0], 1e-10f));

    float* ob = out + (size_t)b * PROJ_DIM;
    for (int i = tid; i < PROJ_DIM; i += 256) {
        float v = Yb[i];
        ob[i] = copysignf(sqrtf(fabsf(v)), v) * inv;
    }
}

// ---------------- launcher ---------------------------------------------------
extern "C" void kernel_launch(void* const* d_in, const int* in_sizes, int n_in,
                              void* d_out, int out_size) {
    const float* x  = (const float*)d_in[0];   // [32,14,14,512]
    const float* M1 = (const float*)d_in[1];   // [512,8192]
    const float* M2 = (const float*)d_in[2];   // [512,8192]
    float* out = (float*)d_out;                // [32,8192]
    (void)in_sizes; (void)n_in; (void)out_size;

    int*   h1; float* s1; int* h2; float* s2;
    cudaGetSymbolAddress((void**)&h1, g_h1);
    cudaGetSymbolAddress((void**)&s1, g_s1);
    cudaGetSymbolAddress((void**)&h2, g_h2);
    cudaGetSymbolAddress((void**)&s2, g_s2);

    // A: extract sketches
    {
        dim3 blk(32, 8);
        extract_kernel<<<64, blk>>>(M1, h1, s1);
        extract_kernel<<<64, blk>>>(M2, h2, s2);
    }
    // B: batched Gram
    {
        dim3 grid(8, 8, BATCH);
        dim3 blk(16, 16);
        gram_kernel<<<grid, blk>>>(x);
    }
    // Z: zero Y
    zero_kernel<<<(BATCH * PROJ_DIM + 255) / 256, 256>>>();
    // C: scatter into circular-conv bins
    {
        dim3 grid(8, BATCH);
        scatter_kernel<<<grid, 256>>>();
    }
    // D: finalize
    finalize_kernel<<<BATCH, 256>>>(out);
}

// round 4
// speedup vs baseline: 1.6743x; 1.6743x over previous
#include <cuda_runtime.h>
#include <math.h>

#define INPUT_DIM 512
#define PROJ_DIM  8192
#define HW        196
#define BATCH     32
#define NPAIRS    (INPUT_DIM * INPUT_DIM)

// ---------------- scratch (device globals; no allocation allowed) -----------
__device__ float g_G[BATCH * INPUT_DIM * INPUT_DIM];   // Gram, batch-major (upper tiles valid)
__device__ float g_T[INPUT_DIM * INPUT_DIM * BATCH];   // Gram, batch-last
__device__ float g_Y[PROJ_DIM * BATCH];                // pooled sketch, [bin][batch]
__device__ int   g_h1[INPUT_DIM], g_h2[INPUT_DIM];
__device__ float g_s1[INPUT_DIM], g_s2[INPUT_DIM];
__device__ int   g_cnt[PROJ_DIM];                      // per-bin pair count
__device__ int   g_off[PROJ_DIM];                      // per-bin exclusive offset
__device__ int   g_cur[PROJ_DIM];                      // fill cursors
__device__ int   g_paddr[NPAIRS];                      // pair -> T base address (elements)
__device__ float g_pscale[NPAIRS];                     // pair -> s1*s2

// ---------------- kernel: zero bin counts ------------------------------------
__global__ void zero_cnt_kernel() {
    int i = blockIdx.x * 256 + threadIdx.x;
    if (i < PROJ_DIM) g_cnt[i] = 0;
}

// ---------------- kernel: extract count-sketch (h, s) from dense M -----------
// one block per row of M [512, 8192]; exactly one nonzero per row
__global__ void extract_kernel(const float* __restrict__ M, int* __restrict__ h,
                               float* __restrict__ s) {
    int row = blockIdx.x;
    const float* r = M + (size_t)row * PROJ_DIM;
    for (int j = threadIdx.x; j < PROJ_DIM; j += blockDim.x) {
        float v = r[j];
        if (v != 0.0f) { h[row] = j; s[row] = v; }
    }
}

// ---------------- kernel: per-pair bin histogram ------------------------------
__global__ void count_kernel() {
    int p = blockIdx.x * 256 + threadIdx.x;     // 0..262143
    int c1 = p >> 9, c2 = p & (INPUT_DIM - 1);
    int k = (g_h1[c1] + g_h2[c2]) & (PROJ_DIM - 1);
    atomicAdd(&g_cnt[k], 1);
}

// ---------------- kernel: exclusive scan over 8192 bins (single block) --------
__global__ void scan_kernel() {
    __shared__ int sm[1024];
    int t = threadIdx.x;
    int base = t * 8;
    int local[8];
    int sum = 0;
#pragma unroll
    for (int i = 0; i < 8; i++) { local[i] = sum; sum += g_cnt[base + i]; }
    sm[t] = sum;
    __syncthreads();
    for (int d = 1; d < 1024; d <<= 1) {
        int v = (t >= d) ? sm[t - d] : 0;
        __syncthreads();
        sm[t] += v;
        __syncthreads();
    }
    int excl = sm[t] - sum;   // exclusive prefix for this thread's 8 bins
#pragma unroll
    for (int i = 0; i < 8; i++) {
        int o = excl + local[i];
        g_off[base + i] = o;
        g_cur[base + i] = o;
    }
}

// ---------------- kernel: fill CSR pair lists ---------------------------------
__global__ void fill_kernel() {
    int p = blockIdx.x * 256 + threadIdx.x;
    int c1 = p >> 9, c2 = p & (INPUT_DIM - 1);
    int k = (g_h1[c1] + g_h2[c2]) & (PROJ_DIM - 1);
    int pos = atomicAdd(&g_cur[k], 1);
    int cmin = min(c1, c2), cmax = max(c1, c2);
    g_paddr[pos]  = (cmin * INPUT_DIM + cmax) * BATCH;
    g_pscale[pos] = g_s1[c1] * g_s2[c2];
}

// ---------------- kernel: batched Gram, upper-triangle tiles only -------------
// x: [32, 196, 512]; block computes a 64x64 tile of G[b]; 256 threads, 4x4/thread
#define TILE 64
#define KB   16
__global__ void gram_kernel(const float* __restrict__ x) {
    int b = blockIdx.y;
    // map blockIdx.x in [0,36) -> (tm, tn) with tm <= tn over 8x8 tiles
    int t = blockIdx.x, tm = 0, rem = 8;
    while (t >= rem) { t -= rem; tm++; rem--; }
    int tn = tm + t;

    __shared__ float As[KB][TILE];
    __shared__ float Bs[KB][TILE];

    const float* xb = x + (size_t)b * HW * INPUT_DIM;
    int tx = threadIdx.x, ty = threadIdx.y;
    int tid = ty * 16 + tx;

    float acc[4][4];
#pragma unroll
    for (int i = 0; i < 4; i++)
#pragma unroll
        for (int j = 0; j < 4; j++) acc[i][j] = 0.0f;

    for (int k0 = 0; k0 < HW; k0 += KB) {
#pragma unroll
        for (int l = 0; l < 4; l++) {
            int idx = tid + l * 256;
            int kk = idx >> 6, cc = idx & 63;
            int k = k0 + kk;
            float a = 0.0f, bb = 0.0f;
            if (k < HW) {
                a  = xb[(size_t)k * INPUT_DIM + tm * TILE + cc];
                bb = xb[(size_t)k * INPUT_DIM + tn * TILE + cc];
            }
            As[kk][cc] = a;
            Bs[kk][cc] = bb;
        }
        __syncthreads();

#pragma unroll
        for (int kk = 0; kk < KB; kk++) {
            float4 av = *reinterpret_cast<const float4*>(&As[kk][ty * 4]);
            float4 bv = *reinterpret_cast<const float4*>(&Bs[kk][tx * 4]);
            float a[4]  = {av.x, av.y, av.z, av.w};
            float bb[4] = {bv.x, bv.y, bv.z, bv.w};
#pragma unroll
            for (int i = 0; i < 4; i++)
#pragma unroll
                for (int j = 0; j < 4; j++) acc[i][j] = fmaf(a[i], bb[j], acc[i][j]);
        }
        __syncthreads();
    }

    float* Gb = g_G + (size_t)b * INPUT_DIM * INPUT_DIM;
#pragma unroll
    for (int i = 0; i < 4; i++) {
        int c1 = tm * TILE + ty * 4 + i;
        float4 v = make_float4(acc[i][0], acc[i][1], acc[i][2], acc[i][3]);
        *reinterpret_cast<float4*>(&Gb[(size_t)c1 * INPUT_DIM + tn * TILE + tx * 4]) = v;
    }
}

// ---------------- kernel: transpose G (batch-major) -> T (batch-last) ---------
// block: 8 c1 x 32 c2 x all 32 batches; smem staged, conflict-free (pad 33)
__global__ void transpose_kernel() {
    __shared__ float sm[8 * 32 * 33];
    int c1b = blockIdx.y * 8;
    int c2b = blockIdx.x * 32;
    if (c1b > c2b + 31) return;   // strictly-lower tiles never read by gather
    int tid = threadIdx.x;
    int lane = tid & 31, w = tid >> 5;

#pragma unroll 4
    for (int i = 0; i < 32; i++) {
        int j = i * 8 + w;              // 0..255
        int b = j >> 3, c1i = j & 7;
        float v = g_G[((size_t)b * INPUT_DIM + (c1b + c1i)) * INPUT_DIM + c2b + lane];
        sm[(c1i * 32 + lane) * 33 + b] = v;
    }
    __syncthreads();
#pragma unroll 4
    for (int i = 0; i < 32; i++) {
        int j = i * 8 + w;
        int c1i = j >> 5, c2i = j & 31;
        float v = sm[(c1i * 32 + c2i) * 33 + lane];
        g_T[((size_t)(c1b + c1i) * INPUT_DIM + (c2b + c2i)) * BATCH + lane] = v;
    }
}

// ---------------- kernel: gather pairs per bin (no atomics) -------------------
// warp per bin, lane per batch; each pair = 1 coalesced 128B load + 1 FMA
__global__ void gather_kernel() {
    int warp = threadIdx.x >> 5, lane = threadIdx.x & 31;
    int bin = blockIdx.x * 8 + warp;
    int off = g_off[bin], cnt = g_cnt[bin];
    float acc = 0.0f;
    int i = 0;
    for (; i + 4 <= cnt; i += 4) {
        int a0 = g_paddr[off + i + 0];
        int a1 = g_paddr[off + i + 1];
        int a2 = g_paddr[off + i + 2];
        int a3 = g_paddr[off + i + 3];
        float s0 = g_pscale[off + i + 0];
        float s1 = g_pscale[off + i + 1];
        float s2 = g_pscale[off + i + 2];
        float s3 = g_pscale[off + i + 3];
        float v0 = g_T[a0 + lane];
        float v1 = g_T[a1 + lane];
        float v2 = g_T[a2 + lane];
        float v3 = g_T[a3 + lane];
        acc = fmaf(s0, v0, acc);
        acc = fmaf(s1, v1, acc);
        acc = fmaf(s2, v2, acc);
        acc = fmaf(s3, v3, acc);
    }
    for (; i < cnt; i++)
        acc = fmaf(g_pscale[off + i], g_T[g_paddr[off + i] + lane], acc);
    g_Y[bin * BATCH + lane] = acc;
}

// ---------------- kernel: signed sqrt + L2 normalize --------------------------
// y = sign(v)*sqrt(|v|) so y^2 = |v|; norm^2 = sum |v|
__global__ void finalize_kernel(float* __restrict__ out) {
    __shared__ float red[256];
    int b = blockIdx.x;
    int tid = threadIdx.x;

    float sum = 0.0f;
    for (int k = tid; k < PROJ_DIM; k += 256) sum += fabsf(g_Y[k * BATCH + b]);
    red[tid] = sum;
    __syncthreads();
    for (int off = 128; off > 0; off >>= 1) {
        if (tid < off) red[tid] += red[tid + off];
        __syncthreads();
    }
    float inv = rsqrtf(fmaxf(red[0], 1e-10f));

    float* ob = out + (size_t)b * PROJ_DIM;
    for (int k = tid; k < PROJ_DIM; k += 256) {
        float v = g_Y[k * BATCH + b];
        ob[k] = copysignf(sqrtf(fabsf(v)), v) * inv;
    }
}

// ---------------- launcher ---------------------------------------------------
extern "C" void kernel_launch(void* const* d_in, const int* in_sizes, int n_in,
                              void* d_out, int out_size) {
    const float* x  = (const float*)d_in[0];   // [32,14,14,512]
    const float* M1 = (const float*)d_in[1];   // [512,8192]
    const float* M2 = (const float*)d_in[2];   // [512,8192]
    float* out = (float*)d_out;                // [32,8192]
    (void)in_sizes; (void)n_in; (void)out_size;

    int* h1; float* s1; int* h2; float* s2;
    cudaGetSymbolAddress((void**)&h1, g_h1);
    cudaGetSymbolAddress((void**)&s1, g_s1);
    cudaGetSymbolAddress((void**)&h2, g_h2);
    cudaGetSymbolAddress((void**)&s2, g_s2);

    // 1,2: extract sketches (block per row)
    extract_kernel<<<INPUT_DIM, 256>>>(M1, h1, s1);
    extract_kernel<<<INPUT_DIM, 256>>>(M2, h2, s2);
    // 3: zero bin counts
    zero_cnt_kernel<<<PROJ_DIM / 256, 256>>>();
    // 4: histogram pairs into bins
    count_kernel<<<NPAIRS / 256, 256>>>();
    // 5: scan -> offsets + cursors
    scan_kernel<<<1, 1024>>>();
    // 6: batched symmetric Gram (6th launch -> ncu -s 5 profiles this)
    {
        dim3 grid(36, BATCH);
        dim3 blk(16, 16);
        gram_kernel<<<grid, blk>>>(x);
    }
    // 7: fill CSR pair lists
    fill_kernel<<<NPAIRS / 256, 256>>>();
    // 8: transpose Gram to batch-last
    {
        dim3 grid(16, 64);
        transpose_kernel<<<grid, 256>>>();
    }
    // 9: gather into bins
    gather_kernel<<<PROJ_DIM / 8, 256>>>();
    // 10: finalize
    finalize_kernel<<<BATCH, 256>>>(out);
}

// round 7
// speedup vs baseline: 2.0991x; 1.2537x over previous
#include <cuda_runtime.h>
#include <cuda_fp16.h>
#include <math.h>
#include <stdint.h>

#define INPUT_DIM 512
#define PROJ_DIM  8192
#define HW        196
#define BATCH     32
#define NPAIRS    (INPUT_DIM * INPUT_DIM)
#define KPAD      448      // 2*196 = 392 padded to 7*64 (interleaved hi/lo fp16 splits)
#define KCHUNK    64
#define NCHUNKS   (KPAD / KCHUNK)

// ---------------- scratch (device globals; no allocation allowed) -----------
__device__ float          g_G[BATCH * INPUT_DIM * INPUT_DIM];  // Gram, batch-major (upper 128-tiles valid)
__device__ float          g_T[INPUT_DIM * INPUT_DIM * BATCH];  // Gram, batch-last
__device__ float          g_Y[PROJ_DIM * BATCH];               // pooled sketch, [bin][batch]
__device__ unsigned short g_xsp[BATCH * INPUT_DIM * KPAD];     // fp16 split-stacked x^T
__device__ int   g_h1[INPUT_DIM], g_h2[INPUT_DIM];
__device__ float g_s1[INPUT_DIM], g_s2[INPUT_DIM];
__device__ int   g_cnt[PROJ_DIM];
__device__ int   g_off[PROJ_DIM];
__device__ int   g_cur[PROJ_DIM];
__device__ int   g_paddr[NPAIRS];
__device__ float g_pscale[NPAIRS];

// ---------------- kernel 1: extract both count-sketches ----------------------
__global__ void extract_both_kernel(const float* __restrict__ M1,
                                    const float* __restrict__ M2) {
    int blk = blockIdx.x;
    const float* M; int* h; float* s; int row;
    if (blk < INPUT_DIM) { M = M1; h = g_h1; s = g_s1; row = blk; }
    else                 { M = M2; h = g_h2; s = g_s2; row = blk - INPUT_DIM; }
    const float* r = M + (size_t)row * PROJ_DIM;
    for (int j = threadIdx.x; j < PROJ_DIM; j += blockDim.x) {
        float v = r[j];
        if (v != 0.0f) { h[row] = j; s[row] = v; }
    }
}

// ---------------- kernel 2: per-pair bin histogram ----------------------------
__global__ void count_kernel() {
    int p = blockIdx.x * 256 + threadIdx.x;
    int c1 = p >> 9, c2 = p & (INPUT_DIM - 1);
    int k = (g_h1[c1] + g_h2[c2]) & (PROJ_DIM - 1);
    atomicAdd(&g_cnt[k], 1);
}

// ---------------- kernel 3: exclusive scan over 8192 bins ---------------------
__global__ void scan_kernel() {
    __shared__ int sm[1024];
    int t = threadIdx.x;
    int base = t * 8;
    int local[8];
    int sum = 0;
#pragma unroll
    for (int i = 0; i < 8; i++) { local[i] = sum; sum += g_cnt[base + i]; }
    sm[t] = sum;
    __syncthreads();
    for (int d = 1; d < 1024; d <<= 1) {
        int v = (t >= d) ? sm[t - d] : 0;
        __syncthreads();
        sm[t] += v;
        __syncthreads();
    }
    int excl = sm[t] - sum;
#pragma unroll
    for (int i = 0; i < 8; i++) {
        int o = excl + local[i];
        g_off[base + i] = o;
        g_cur[base + i] = o;
    }
}

// ---------------- kernel 4: fill CSR pair lists -------------------------------
__global__ void fill_kernel() {
    int p = blockIdx.x * 256 + threadIdx.x;
    int c1 = p >> 9, c2 = p & (INPUT_DIM - 1);
    int k = (g_h1[c1] + g_h2[c2]) & (PROJ_DIM - 1);
    int pos = atomicAdd(&g_cur[k], 1);
    int cmin = min(c1, c2), cmax = max(c1, c2);
    g_paddr[pos]  = (cmin * INPUT_DIM + cmax) * BATCH;
    g_pscale[pos] = g_s1[c1] * g_s2[c2];
}

// ---------------- kernel 5: prep — fp16 split + transpose to [b][c][kk] -------
// kk = 2*hw -> hi split, 2*hw+1 -> lo split; kk in [392,448) zero padding
__global__ void prep_split_kernel(const float* __restrict__ x) {
    __shared__ float sm[64][65];
    int b = blockIdx.z, hwt = blockIdx.y, ct = blockIdx.x;
    int hw0 = hwt * 64, c0 = ct * 64;
    int t = threadIdx.x;

#pragma unroll
    for (int p = 0; p < 4; p++) {
        int row = p * 16 + (t >> 4);
        int col = (t & 15) * 4;
        int hw = hw0 + row;
        float4 v = make_float4(0.f, 0.f, 0.f, 0.f);
        if (hw < HW)
            v = *(const float4*)(x + ((size_t)(b * HW + hw)) * INPUT_DIM + c0 + col);
        sm[row][col] = v.x; sm[row][col + 1] = v.y;
        sm[row][col + 2] = v.z; sm[row][col + 3] = v.w;
    }
    __syncthreads();

    int c_i = t >> 2, q = t & 3;
    int kkbase = 2 * hw0 + q * 32;     // 32 kk = 16 hw
    if (kkbase < KPAD) {
        uint32_t outw[16];
#pragma unroll
        for (int i = 0; i < 16; i++) {
            int hwl = q * 16 + i;
            float v = (hw0 + hwl < HW) ? sm[hwl][c_i] : 0.0f;
            __half h1 = __float2half_rn(v);
            float r = v - __half2float(h1);
            __half h2 = __float2half_rn(r);
            outw[i] = ((uint32_t)__half_as_ushort(h2) << 16) |
                      (uint32_t)__half_as_ushort(h1);
        }
        uint4* dst = (uint4*)(g_xsp + ((size_t)(b * INPUT_DIM + c0 + c_i)) * KPAD + kkbase);
        const uint4* s = (const uint4*)outw;
        dst[0] = s[0]; dst[1] = s[1]; dst[2] = s[2]; dst[3] = s[3];
    }
}

// ---------------- kernel 6: HMMA fp16 Gram, upper 128x128 tiles ---------------
// block = 256 thr = 8 warps (2 m x 4 n); warp tile 64x32 via m16n8k16
#define SPITCH 72   // smem row pitch in fp16 elems (conflict-free, 16B-aligned rows)
__global__ __launch_bounds__(256) void gram_hmma_kernel() {
    __shared__ __align__(16) unsigned short As[128 * SPITCH];
    __shared__ __align__(16) unsigned short Bs[128 * SPITCH];

    int b = blockIdx.y;
    int tt = blockIdx.x, tm = 0, rem = 4;
    while (tt >= rem) { tt -= rem; tm++; rem--; }
    int tn = tm + tt;

    int t = threadIdx.x, lane = t & 31, wid = t >> 5;
    int warp_m = wid & 1, warp_n = wid >> 1;

    float acc[4][4][4];
#pragma unroll
    for (int mi = 0; mi < 4; mi++)
#pragma unroll
        for (int ni = 0; ni < 4; ni++)
#pragma unroll
            for (int j = 0; j < 4; j++) acc[mi][ni][j] = 0.0f;

    const unsigned short* baseA = g_xsp + ((size_t)(b * INPUT_DIM + tm * 128)) * KPAD;
    const unsigned short* baseB = g_xsp + ((size_t)(b * INPUT_DIM + tn * 128)) * KPAD;

    for (int ch = 0; ch < NCHUNKS; ch++) {
        int k0 = ch * KCHUNK;
#pragma unroll
        for (int i = 0; i < 4; i++) {
            int u = i * 256 + t;
            int row = u >> 3, j = u & 7;     // 8 uint4 (=64 fp16) per row
            *(uint4*)(As + row * SPITCH + j * 8) =
                *(const uint4*)(baseA + (size_t)row * KPAD + k0 + j * 8);
            *(uint4*)(Bs + row * SPITCH + j * 8) =
                *(const uint4*)(baseB + (size_t)row * KPAD + k0 + j * 8);
        }
        __syncthreads();

#pragma unroll
        for (int kk = 0; kk < 4; kk++) {
            int krow = kk * 16 + (lane & 3) * 2;
            uint32_t afr[4][4];
#pragma unroll
            for (int mi = 0; mi < 4; mi++) {
                int r0 = warp_m * 64 + mi * 16 + (lane >> 2);
                afr[mi][0] = *(const uint32_t*)(As + r0 * SPITCH + krow);
                afr[mi][1] = *(const uint32_t*)(As + (r0 + 8) * SPITCH + krow);
                afr[mi][2] = *(const uint32_t*)(As + r0 * SPITCH + krow + 8);
                afr[mi][3] = *(const uint32_t*)(As + (r0 + 8) * SPITCH + krow + 8);
            }
            uint32_t bfr[4][2];
#pragma unroll
            for (int ni = 0; ni < 4; ni++) {
                int rn = warp_n * 32 + ni * 8 + (lane >> 2);
                bfr[ni][0] = *(const uint32_t*)(Bs + rn * SPITCH + krow);
                bfr[ni][1] = *(const uint32_t*)(Bs + rn * SPITCH + krow + 8);
            }
#pragma unroll
            for (int mi = 0; mi < 4; mi++)
#pragma unroll
                for (int ni = 0; ni < 4; ni++) {
                    asm volatile(
                        "mma.sync.aligned.m16n8k16.row.col.f32.f16.f16.f32 "
                        "{%0,%1,%2,%3}, {%4,%5,%6,%7}, {%8,%9}, {%0,%1,%2,%3};"
                        : "+f"(acc[mi][ni][0]), "+f"(acc[mi][ni][1]),
                          "+f"(acc[mi][ni][2]), "+f"(acc[mi][ni][3])
                        : "r"(afr[mi][0]), "r"(afr[mi][1]),
                          "r"(afr[mi][2]), "r"(afr[mi][3]),
                          "r"(bfr[ni][0]), "r"(bfr[ni][1]));
                }
        }
        __syncthreads();
    }

    // epilogue: D frag (m = lane>>2 (+8), n = (lane&3)*2 (+1))
    int c1b = tm * 128 + warp_m * 64;
    int c2b = tn * 128 + warp_n * 32;
    int r = lane >> 2, cc = (lane & 3) * 2;
#pragma unroll
    for (int mi = 0; mi < 4; mi++) {
#pragma unroll
        for (int ni = 0; ni < 4; ni++) {
            float* d0 = g_G + ((size_t)(b * INPUT_DIM + c1b + mi * 16 + r)) * INPUT_DIM
                        + c2b + ni * 8 + cc;
            *(float2*)d0 = make_float2(acc[mi][ni][0], acc[mi][ni][1]);
            float* d1 = d0 + 8 * INPUT_DIM;
            *(float2*)d1 = make_float2(acc[mi][ni][2], acc[mi][ni][3]);
        }
    }
}

// ---------------- kernel 7: transpose G (batch-major) -> T (batch-last) ------
__global__ void transpose_kernel() {
    __shared__ float sm[8 * 32 * 33];
    int c1b = blockIdx.y * 8;
    int c2b = blockIdx.x * 32;
    if (c1b > c2b + 31) return;
    int tid = threadIdx.x;
    int lane = tid & 31, w = tid >> 5;

#pragma unroll 4
    for (int i = 0; i < 32; i++) {
        int j = i * 8 + w;
        int b = j >> 3, c1i = j & 7;
        float v = g_G[((size_t)b * INPUT_DIM + (c1b + c1i)) * INPUT_DIM + c2b + lane];
        sm[(c1i * 32 + lane) * 33 + b] = v;
    }
    __syncthreads();
#pragma unroll 4
    for (int i = 0; i < 32; i++) {
        int j = i * 8 + w;
        int c1i = j >> 5, c2i = j & 31;
        float v = sm[(c1i * 32 + c2i) * 33 + lane];
        g_T[((size_t)(c1b + c1i) * INPUT_DIM + (c2b + c2i)) * BATCH + lane] = v;
    }
}

// ---------------- kernel 8: gather pairs per bin (no atomics) -----------------
__global__ void gather_kernel() {
    int warp = threadIdx.x >> 5, lane = threadIdx.x & 31;
    int bin = blockIdx.x * 8 + warp;
    int off = g_off[bin], cnt = g_cnt[bin];
    float acc = 0.0f;
    int i = 0;
    for (; i + 4 <= cnt; i += 4) {
        int a0 = g_paddr[off + i + 0];
        int a1 = g_paddr[off + i + 1];
        int a2 = g_paddr[off + i + 2];
        int a3 = g_paddr[off + i + 3];
        float s0 = g_pscale[off + i + 0];
        float s1 = g_pscale[off + i + 1];
        float s2 = g_pscale[off + i + 2];
        float s3 = g_pscale[off + i + 3];
        float v0 = g_T[a0 + lane];
        float v1 = g_T[a1 + lane];
        float v2 = g_T[a2 + lane];
        float v3 = g_T[a3 + lane];
        acc = fmaf(s0, v0, acc);
        acc = fmaf(s1, v1, acc);
        acc = fmaf(s2, v2, acc);
        acc = fmaf(s3, v3, acc);
    }
    for (; i < cnt; i++)
        acc = fmaf(g_pscale[off + i], g_T[g_paddr[off + i] + lane], acc);
    g_Y[bin * BATCH + lane] = acc;
}

// ---------------- kernel 9: signed sqrt + L2 normalize ------------------------
__global__ void finalize_kernel(float* __restrict__ out) {
    __shared__ float red[256];
    int b = blockIdx.x;
    int tid = threadIdx.x;

    float sum = 0.0f;
    for (int k = tid; k < PROJ_DIM; k += 256) sum += fabsf(g_Y[k * BATCH + b]);
    red[tid] = sum;
    __syncthreads();
    for (int off = 128; off > 0; off >>= 1) {
        if (tid < off) red[tid] += red[tid + off];
        __syncthreads();
    }
    float inv = rsqrtf(fmaxf(red[0], 1e-10f));

    float* ob = out + (size_t)b * PROJ_DIM;
    for (int k = tid; k < PROJ_DIM; k += 256) {
        float v = g_Y[k * BATCH + b];
        ob[k] = copysignf(sqrtf(fabsf(v)), v) * inv;
    }
}

// ---------------- launcher ---------------------------------------------------
extern "C" void kernel_launch(void* const* d_in, const int* in_sizes, int n_in,
                              void* d_out, int out_size) {
    const float* x  = (const float*)d_in[0];   // [32,14,14,512]
    const float* M1 = (const float*)d_in[1];   // [512,8192]
    const float* M2 = (const float*)d_in[2];   // [512,8192]
    float* out = (float*)d_out;                // [32,8192]
    (void)in_sizes; (void)n_in; (void)out_size;

    void* cnt_addr;
    cudaGetSymbolAddress(&cnt_addr, g_cnt);

    // 1: extract both sketches
    extract_both_kernel<<<2 * INPUT_DIM, 256>>>(M1, M2);
    // memset node: zero bin counts
    cudaMemsetAsync(cnt_addr, 0, PROJ_DIM * sizeof(int));
    // 2: histogram pairs
    count_kernel<<<NPAIRS / 256, 256>>>();
    // 3: scan
    scan_kernel<<<1, 1024>>>();
    // 4: fill CSR
    fill_kernel<<<NPAIRS / 256, 256>>>();
    // 5: fp16 split + transpose
    {
        dim3 grid(8, 4, BATCH);
        prep_split_kernel<<<grid, 256>>>(x);
    }
    // 6: tensor-core Gram (HMMA mma.sync — compute_103-safe)
    {
        dim3 grid(10, BATCH);
        gram_hmma_kernel<<<grid, 256>>>();
    }
    // 7: transpose to batch-last
    {
        dim3 grid(16, 64);
        transpose_kernel<<<grid, 256>>>();
    }
    // 8: gather
    gather_kernel<<<PROJ_DIM / 8, 256>>>();
    // 9: finalize
    finalize_kernel<<<BATCH, 256>>>(out);
}

// round 8
// speedup vs baseline: 2.6505x; 1.2627x over previous
#include <cuda_runtime.h>
#include <cuda_fp16.h>
#include <math.h>
#include <stdint.h>

#define INPUT_DIM 512
#define PROJ_DIM  8192
#define HW        196
#define BATCH     32
#define NPAIRS    (INPUT_DIM * INPUT_DIM)
#define KPAD      448      // 2*196 = 392 padded to 7*64 (interleaved hi/lo fp16 splits)
#define KCHUNK    64
#define NCHUNKS   (KPAD / KCHUNK)
#define CAP       128      // bucket capacity (mean 32, Poisson tail ~0 at 128)

// ---------------- scratch (device globals; no allocation allowed) -----------
__device__ float          g_G[BATCH * INPUT_DIM * INPUT_DIM];  // Gram, batch-major (upper 128-tiles valid)
__device__ float          g_T[INPUT_DIM * INPUT_DIM * BATCH];  // Gram, batch-last
__device__ float          g_Y[PROJ_DIM * BATCH];               // pooled sketch, [bin][batch]
__device__ unsigned short g_xsp[BATCH * INPUT_DIM * KPAD];     // fp16 split-stacked x^T
__device__ int   g_h1[INPUT_DIM], g_h2[INPUT_DIM];
__device__ float g_s1[INPUT_DIM], g_s2[INPUT_DIM];
__device__ int   g_cnt[PROJ_DIM];                              // per-bin pair count
__device__ int2  g_pairs[PROJ_DIM * CAP];                      // {T-address, scale bits}
__device__ float g_norm[BATCH];                                // sum |Y| per batch

// ---------------- kernel 1: extract both count-sketches ----------------------
__global__ void extract_both_kernel(const float* __restrict__ M1,
                                    const float* __restrict__ M2) {
    int blk = blockIdx.x;
    const float* M; int* h; float* s; int row;
    if (blk < INPUT_DIM) { M = M1; h = g_h1; s = g_s1; row = blk; }
    else                 { M = M2; h = g_h2; s = g_s2; row = blk - INPUT_DIM; }
    const float* r = M + (size_t)row * PROJ_DIM;
    for (int j = threadIdx.x; j < PROJ_DIM; j += blockDim.x) {
        float v = r[j];
        if (v != 0.0f) { h[row] = j; s[row] = v; }
    }
}

// ---------------- kernel 2: fill buckets (single pass, no scan) ---------------
// 65536 threads, 4 consecutive c2 per thread -> independent atomics in flight
__global__ void fill_kernel() {
    int t = blockIdx.x * 256 + threadIdx.x;
    int c1  = t >> 7;
    int c2b = (t & 127) * 4;
    int   h1 = g_h1[c1];
    float s1 = g_s1[c1];
#pragma unroll
    for (int i = 0; i < 4; i++) {
        int c2 = c2b + i;
        int k = (h1 + g_h2[c2]) & (PROJ_DIM - 1);
        int pos = atomicAdd(&g_cnt[k], 1);
        if (pos < CAP) {
            int cmin = min(c1, c2), cmax = max(c1, c2);
            g_pairs[k * CAP + pos] =
                make_int2((cmin * INPUT_DIM + cmax) * BATCH,
                          __float_as_int(s1 * g_s2[c2]));
        }
    }
}

// ---------------- kernel 3: prep — fp16 split + transpose to [b][c][kk] -------
// kk = 2*hw -> hi split, 2*hw+1 -> lo split; kk in [392,448) zero padding
__global__ void prep_split_kernel(const float* __restrict__ x) {
    __shared__ float sm[64][65];
    int b = blockIdx.z, hwt = blockIdx.y, ct = blockIdx.x;
    int hw0 = hwt * 64, c0 = ct * 64;
    int t = threadIdx.x;

#pragma unroll
    for (int p = 0; p < 4; p++) {
        int row = p * 16 + (t >> 4);
        int col = (t & 15) * 4;
        int hw = hw0 + row;
        float4 v = make_float4(0.f, 0.f, 0.f, 0.f);
        if (hw < HW)
            v = *(const float4*)(x + ((size_t)(b * HW + hw)) * INPUT_DIM + c0 + col);
        sm[row][col] = v.x; sm[row][col + 1] = v.y;
        sm[row][col + 2] = v.z; sm[row][col + 3] = v.w;
    }
    __syncthreads();

    int c_i = t >> 2, q = t & 3;
    int kkbase = 2 * hw0 + q * 32;     // 32 kk = 16 hw
    if (kkbase < KPAD) {
        uint32_t outw[16];
#pragma unroll
        for (int i = 0; i < 16; i++) {
            int hwl = q * 16 + i;
            float v = (hw0 + hwl < HW) ? sm[hwl][c_i] : 0.0f;
            __half h1 = __float2half_rn(v);
            float r = v - __half2float(h1);
            __half h2 = __float2half_rn(r);
            outw[i] = ((uint32_t)__half_as_ushort(h2) << 16) |
                      (uint32_t)__half_as_ushort(h1);
        }
        uint4* dst = (uint4*)(g_xsp + ((size_t)(b * INPUT_DIM + c0 + c_i)) * KPAD + kkbase);
        const uint4* s = (const uint4*)outw;
        dst[0] = s[0]; dst[1] = s[1]; dst[2] = s[2]; dst[3] = s[3];
    }
}

// ---------------- kernel 4: HMMA fp16 Gram, upper 128x128 tiles ---------------
// block = 256 thr = 8 warps (2 m x 4 n); warp tile 64x32 via m16n8k16
#define SPITCH 72   // smem row pitch in fp16 elems (conflict-free, 16B-aligned rows)
__global__ __launch_bounds__(256) void gram_hmma_kernel() {
    __shared__ __align__(16) unsigned short As[128 * SPITCH];
    __shared__ __align__(16) unsigned short Bs[128 * SPITCH];

    int b = blockIdx.y;
    int tt = blockIdx.x, tm = 0, rem = 4;
    while (tt >= rem) { tt -= rem; tm++; rem--; }
    int tn = tm + tt;

    int t = threadIdx.x, lane = t & 31, wid = t >> 5;
    int warp_m = wid & 1, warp_n = wid >> 1;

    float acc[4][4][4];
#pragma unroll
    for (int mi = 0; mi < 4; mi++)
#pragma unroll
        for (int ni = 0; ni < 4; ni++)
#pragma unroll
            for (int j = 0; j < 4; j++) acc[mi][ni][j] = 0.0f;

    const unsigned short* baseA = g_xsp + ((size_t)(b * INPUT_DIM + tm * 128)) * KPAD;
    const unsigned short* baseB = g_xsp + ((size_t)(b * INPUT_DIM + tn * 128)) * KPAD;

    for (int ch = 0; ch < NCHUNKS; ch++) {
        int k0 = ch * KCHUNK;
#pragma unroll
        for (int i = 0; i < 4; i++) {
            int u = i * 256 + t;
            int row = u >> 3, j = u & 7;     // 8 uint4 (=64 fp16) per row
            *(uint4*)(As + row * SPITCH + j * 8) =
                *(const uint4*)(baseA + (size_t)row * KPAD + k0 + j * 8);
            *(uint4*)(Bs + row * SPITCH + j * 8) =
                *(const uint4*)(baseB + (size_t)row * KPAD + k0 + j * 8);
        }
        __syncthreads();

#pragma unroll
        for (int kk = 0; kk < 4; kk++) {
            int krow = kk * 16 + (lane & 3) * 2;
            uint32_t afr[4][4];
#pragma unroll
            for (int mi = 0; mi < 4; mi++) {
                int r0 = warp_m * 64 + mi * 16 + (lane >> 2);
                afr[mi][0] = *(const uint32_t*)(As + r0 * SPITCH + krow);
                afr[mi][1] = *(const uint32_t*)(As + (r0 + 8) * SPITCH + krow);
                afr[mi][2] = *(const uint32_t*)(As + r0 * SPITCH + krow + 8);
                afr[mi][3] = *(const uint32_t*)(As + (r0 + 8) * SPITCH + krow + 8);
            }
            uint32_t bfr[4][2];
#pragma unroll
            for (int ni = 0; ni < 4; ni++) {
                int rn = warp_n * 32 + ni * 8 + (lane >> 2);
                bfr[ni][0] = *(const uint32_t*)(Bs + rn * SPITCH + krow);
                bfr[ni][1] = *(const uint32_t*)(Bs + rn * SPITCH + krow + 8);
            }
#pragma unroll
            for (int mi = 0; mi < 4; mi++)
#pragma unroll
                for (int ni = 0; ni < 4; ni++) {
                    asm volatile(
                        "mma.sync.aligned.m16n8k16.row.col.f32.f16.f16.f32 "
                        "{%0,%1,%2,%3}, {%4,%5,%6,%7}, {%8,%9}, {%0,%1,%2,%3};"
                        : "+f"(acc[mi][ni][0]), "+f"(acc[mi][ni][1]),
                          "+f"(acc[mi][ni][2]), "+f"(acc[mi][ni][3])
                        : "r"(afr[mi][0]), "r"(afr[mi][1]),
                          "r"(afr[mi][2]), "r"(afr[mi][3]),
                          "r"(bfr[ni][0]), "r"(bfr[ni][1]));
                }
        }
        __syncthreads();
    }

    // epilogue: D frag (m = lane>>2 (+8), n = (lane&3)*2 (+1))
    int c1b = tm * 128 + warp_m * 64;
    int c2b = tn * 128 + warp_n * 32;
    int r = lane >> 2, cc = (lane & 3) * 2;
#pragma unroll
    for (int mi = 0; mi < 4; mi++) {
#pragma unroll
        for (int ni = 0; ni < 4; ni++) {
            float* d0 = g_G + ((size_t)(b * INPUT_DIM + c1b + mi * 16 + r)) * INPUT_DIM
                        + c2b + ni * 8 + cc;
            *(float2*)d0 = make_float2(acc[mi][ni][0], acc[mi][ni][1]);
            float* d1 = d0 + 8 * INPUT_DIM;
            *(float2*)d1 = make_float2(acc[mi][ni][2], acc[mi][ni][3]);
        }
    }
}

// ---------------- kernel 5: transpose G (batch-major) -> T (batch-last) ------
__global__ void transpose_kernel() {
    __shared__ float sm[8 * 32 * 33];
    int c1b = blockIdx.y * 8;
    int c2b = blockIdx.x * 32;
    if (c1b > c2b + 31) return;
    int tid = threadIdx.x;
    int lane = tid & 31, w = tid >> 5;

#pragma unroll 4
    for (int i = 0; i < 32; i++) {
        int j = i * 8 + w;
        int b = j >> 3, c1i = j & 7;
        float v = g_G[((size_t)b * INPUT_DIM + (c1b + c1i)) * INPUT_DIM + c2b + lane];
        sm[(c1i * 32 + lane) * 33 + b] = v;
    }
    __syncthreads();
#pragma unroll 4
    for (int i = 0; i < 32; i++) {
        int j = i * 8 + w;
        int c1i = j >> 5, c2i = j & 31;
        float v = sm[(c1i * 32 + c2i) * 33 + lane];
        g_T[((size_t)(c1b + c1i) * INPUT_DIM + (c2b + c2i)) * BATCH + lane] = v;
    }
}

// ---------------- kernel 6: gather pairs per bin + norm reduce ----------------
// warp per bin, lane per batch; fused |Y| block-reduce -> g_norm atomics
__global__ void gather_kernel() {
    __shared__ float sums[8][33];
    int warp = threadIdx.x >> 5, lane = threadIdx.x & 31;
    int bin = blockIdx.x * 8 + warp;
    int cnt = min(g_cnt[bin], CAP);
    const int2* pl = g_pairs + bin * CAP;
    float acc = 0.0f;
    int i = 0;
    for (; i + 4 <= cnt; i += 4) {
        int2 p0 = pl[i + 0];
        int2 p1 = pl[i + 1];
        int2 p2 = pl[i + 2];
        int2 p3 = pl[i + 3];
        float v0 = g_T[p0.x + lane];
        float v1 = g_T[p1.x + lane];
        float v2 = g_T[p2.x + lane];
        float v3 = g_T[p3.x + lane];
        acc = fmaf(__int_as_float(p0.y), v0, acc);
        acc = fmaf(__int_as_float(p1.y), v1, acc);
        acc = fmaf(__int_as_float(p2.y), v2, acc);
        acc = fmaf(__int_as_float(p3.y), v3, acc);
    }
    for (; i < cnt; i++) {
        int2 p = pl[i];
        acc = fmaf(__int_as_float(p.y), g_T[p.x + lane], acc);
    }
    g_Y[bin * BATCH + lane] = acc;
    sums[warp][lane] = fabsf(acc);
    __syncthreads();
    if (warp == 0) {
        float s = 0.0f;
#pragma unroll
        for (int w = 0; w < 8; w++) s += sums[w][lane];
        atomicAdd(&g_norm[lane], s);
    }
}

// ---------------- kernel 7: signed sqrt + L2 normalize (parallel) -------------
// block = 32 bins x 32 batches, smem transpose, coalesced in and out
__global__ void scale_kernel(float* __restrict__ out) {
    __shared__ float sm[32][33];
    int bin0 = blockIdx.x * 32;
    int lane = threadIdx.x & 31, w = threadIdx.x >> 5;   // 8 warps

#pragma unroll
    for (int r = w; r < 32; r += 8)
        sm[r][lane] = g_Y[(bin0 + r) * BATCH + lane];
    __syncthreads();

#pragma unroll
    for (int b = w; b < 32; b += 8) {
        float inv = rsqrtf(fmaxf(g_norm[b], 1e-10f));
        float v = sm[lane][b];
        out[(size_t)b * PROJ_DIM + bin0 + lane] = copysignf(sqrtf(fabsf(v)), v) * inv;
    }
}

// ---------------- launcher ---------------------------------------------------
extern "C" void kernel_launch(void* const* d_in, const int* in_sizes, int n_in,
                              void* d_out, int out_size) {
    const float* x  = (const float*)d_in[0];   // [32,14,14,512]
    const float* M1 = (const float*)d_in[1];   // [512,8192]
    const float* M2 = (const float*)d_in[2];   // [512,8192]
    float* out = (float*)d_out;                // [32,8192]
    (void)in_sizes; (void)n_in; (void)out_size;

    void* cnt_addr; void* norm_addr;
    cudaGetSymbolAddress(&cnt_addr, g_cnt);
    cudaGetSymbolAddress(&norm_addr, g_norm);
    cudaMemsetAsync(cnt_addr, 0, PROJ_DIM * sizeof(int));
    cudaMemsetAsync(norm_addr, 0, BATCH * sizeof(float));

    // k1: extract both sketches
    extract_both_kernel<<<2 * INPUT_DIM, 256>>>(M1, M2);
    // k2: fill buckets (single pass)
    fill_kernel<<<NPAIRS / 1024, 256>>>();
    // k3: fp16 split + transpose
    {
        dim3 grid(8, 4, BATCH);
        prep_split_kernel<<<grid, 256>>>(x);
    }
    // k4: tensor-core Gram (4th kernel -> profiled by ncu)
    {
        dim3 grid(10, BATCH);
        gram_hmma_kernel<<<grid, 256>>>();
    }
    // k5: transpose to batch-last
    {
        dim3 grid(16, 64);
        transpose_kernel<<<grid, 256>>>();
    }
    // k6: gather + norm reduce
    gather_kernel<<<PROJ_DIM / 8, 256>>>();
    // k7: scale
    scale_kernel<<<PROJ_DIM / 32, 256>>>(out);
}

// round 9
// speedup vs baseline: 2.9502x; 1.1131x over previous
#include <cuda_runtime.h>
#include <cuda_fp16.h>
#include <math.h>
#include <stdint.h>

#define INPUT_DIM 512
#define PROJ_DIM  8192
#define HW        196
#define BATCH     32
#define NPAIRS    (INPUT_DIM * INPUT_DIM)
#define KPAD      448      // 2*196 = 392 padded to 7*64 (interleaved hi/lo fp16 splits)
#define KCHUNK    64
#define NCHUNKS   (KPAD / KCHUNK)
#define CAP       128      // bucket capacity (mean 32, Poisson tail ~0 at 128)

// ---------------- scratch (device globals; no allocation allowed) -----------
__device__ float          g_G[BATCH * INPUT_DIM * INPUT_DIM];  // Gram, batch-major (upper 128-tiles valid)
__device__ float          g_T[INPUT_DIM * INPUT_DIM * BATCH];  // Gram, batch-last
__device__ float          g_Y[PROJ_DIM * BATCH];               // pooled sketch, [bin][batch]
__device__ unsigned short g_xsp[BATCH * INPUT_DIM * KPAD];     // fp16 split-stacked x^T
__device__ int   g_h1[INPUT_DIM], g_h2[INPUT_DIM];
__device__ float g_s1[INPUT_DIM], g_s2[INPUT_DIM];
__device__ int   g_cnt[PROJ_DIM];                              // per-bin pair count
__device__ int2  g_pairs[PROJ_DIM * CAP];                      // {T-address, scale bits}
__device__ float g_norm[BATCH];                                // sum |Y| per batch

// ---------------- kernel 1: extract both count-sketches ----------------------
__global__ void extract_both_kernel(const float* __restrict__ M1,
                                    const float* __restrict__ M2) {
    int blk = blockIdx.x;
    const float* M; int* h; float* s; int row;
    if (blk < INPUT_DIM) { M = M1; h = g_h1; s = g_s1; row = blk; }
    else                 { M = M2; h = g_h2; s = g_s2; row = blk - INPUT_DIM; }
    const float* r = M + (size_t)row * PROJ_DIM;
    for (int j = threadIdx.x; j < PROJ_DIM; j += blockDim.x) {
        float v = r[j];
        if (v != 0.0f) { h[row] = j; s[row] = v; }
    }
}

// ---------------- kernel 2: fill buckets (single pass, no scan) ---------------
__global__ void fill_kernel() {
    int t = blockIdx.x * 256 + threadIdx.x;
    int c1  = t >> 7;
    int c2b = (t & 127) * 4;
    int   h1 = g_h1[c1];
    float s1 = g_s1[c1];
#pragma unroll
    for (int i = 0; i < 4; i++) {
        int c2 = c2b + i;
        int k = (h1 + g_h2[c2]) & (PROJ_DIM - 1);
        int pos = atomicAdd(&g_cnt[k], 1);
        if (pos < CAP) {
            int cmin = min(c1, c2), cmax = max(c1, c2);
            g_pairs[k * CAP + pos] =
                make_int2((cmin * INPUT_DIM + cmax) * BATCH,
                          __float_as_int(s1 * g_s2[c2]));
        }
    }
}

// ---------------- kernel 3: prep — fp16 split + transpose to [b][c][kk] -------
__global__ void prep_split_kernel(const float* __restrict__ x) {
    __shared__ float sm[64][65];
    int b = blockIdx.z, hwt = blockIdx.y, ct = blockIdx.x;
    int hw0 = hwt * 64, c0 = ct * 64;
    int t = threadIdx.x;

#pragma unroll
    for (int p = 0; p < 4; p++) {
        int row = p * 16 + (t >> 4);
        int col = (t & 15) * 4;
        int hw = hw0 + row;
        float4 v = make_float4(0.f, 0.f, 0.f, 0.f);
        if (hw < HW)
            v = *(const float4*)(x + ((size_t)(b * HW + hw)) * INPUT_DIM + c0 + col);
        sm[row][col] = v.x; sm[row][col + 1] = v.y;
        sm[row][col + 2] = v.z; sm[row][col + 3] = v.w;
    }
    __syncthreads();

    int c_i = t >> 2, q = t & 3;
    int kkbase = 2 * hw0 + q * 32;     // 32 kk = 16 hw
    if (kkbase < KPAD) {
        uint32_t outw[16];
#pragma unroll
        for (int i = 0; i < 16; i++) {
            int hwl = q * 16 + i;
            float v = (hw0 + hwl < HW) ? sm[hwl][c_i] : 0.0f;
            __half h1 = __float2half_rn(v);
            float r = v - __half2float(h1);
            __half h2 = __float2half_rn(r);
            outw[i] = ((uint32_t)__half_as_ushort(h2) << 16) |
                      (uint32_t)__half_as_ushort(h1);
        }
        uint4* dst = (uint4*)(g_xsp + ((size_t)(b * INPUT_DIM + c0 + c_i)) * KPAD + kkbase);
        const uint4* s = (const uint4*)outw;
        dst[0] = s[0]; dst[1] = s[1]; dst[2] = s[2]; dst[3] = s[3];
    }
}

// ---------------- kernel 4: HMMA fp16 Gram, ldmatrix + cp.async pipeline ------
#define SPITCH    72                 // fp16 elems per smem row (conflict-free)
#define TILE_ELEM (128 * SPITCH)     // 9216 fp16 per tile
#define BUF_ELEM  (2 * TILE_ELEM)    // A + B per buffer

__device__ __forceinline__ void cp16(void* dst, const void* src) {
    uint32_t d = (uint32_t)__cvta_generic_to_shared(dst);
    asm volatile("cp.async.cg.shared.global [%0], [%1], 16;" :: "r"(d), "l"(src));
}
__device__ __forceinline__ void ldsm4(uint32_t* r, const void* p) {
    uint32_t a = (uint32_t)__cvta_generic_to_shared(p);
    asm volatile("ldmatrix.sync.aligned.m8n8.x4.shared.b16 {%0,%1,%2,%3}, [%4];"
                 : "=r"(r[0]), "=r"(r[1]), "=r"(r[2]), "=r"(r[3]) : "r"(a));
}

__global__ __launch_bounds__(256) void gram_hmma_kernel() {
    extern __shared__ __align__(16) unsigned short smh[];

    int b = blockIdx.y;
    int tt = blockIdx.x, tm = 0, rem = 4;
    while (tt >= rem) { tt -= rem; tm++; rem--; }
    int tn = tm + tt;
    bool diag = (tm == tn);

    int t = threadIdx.x, lane = t & 31, wid = t >> 5;
    int warp_m = wid & 1, warp_n = wid >> 1;

    float acc[4][4][4];
#pragma unroll
    for (int mi = 0; mi < 4; mi++)
#pragma unroll
        for (int ni = 0; ni < 4; ni++)
#pragma unroll
            for (int j = 0; j < 4; j++) acc[mi][ni][j] = 0.0f;

    const unsigned short* baseA = g_xsp + ((size_t)(b * INPUT_DIM + tm * 128)) * KPAD;
    const unsigned short* baseB = g_xsp + ((size_t)(b * INPUT_DIM + tn * 128)) * KPAD;

    // ldmatrix lane addressing (constant offsets per warp)
    int arow = (lane & 7) + ((lane >> 3) & 1) * 8;   // row within 16-row frag
    int acol = (lane >> 4) * 8;                      // 0 or 8 within k16
    int brow = (lane & 7) + (lane >> 4) * 8;
    int bcol = ((lane >> 3) & 1) * 8;

    // load chunk ch into buffer buf (async)
    auto load_chunk = [&](int buf, int ch) {
        unsigned short* dA = smh + buf * BUF_ELEM;
        const unsigned short* sA = baseA + ch * KCHUNK;
#pragma unroll
        for (int i = 0; i < 4; i++) {
            int u = i * 256 + t;
            int row = u >> 3, j = u & 7;
            cp16(dA + row * SPITCH + j * 8, sA + (size_t)row * KPAD + j * 8);
        }
        if (!diag) {
            unsigned short* dB = dA + TILE_ELEM;
            const unsigned short* sB = baseB + ch * KCHUNK;
#pragma unroll
            for (int i = 0; i < 4; i++) {
                int u = i * 256 + t;
                int row = u >> 3, j = u & 7;
                cp16(dB + row * SPITCH + j * 8, sB + (size_t)row * KPAD + j * 8);
            }
        }
    };

    load_chunk(0, 0);
    asm volatile("cp.async.commit_group;");

    int buf = 0;
    for (int ch = 0; ch < NCHUNKS; ch++) {
        if (ch + 1 < NCHUNKS) {
            load_chunk(buf ^ 1, ch + 1);
            asm volatile("cp.async.commit_group;");
            asm volatile("cp.async.wait_group 1;");
        } else {
            asm volatile("cp.async.wait_group 0;");
        }
        __syncthreads();

        const unsigned short* sA = smh + buf * BUF_ELEM;
        const unsigned short* sB = diag ? sA : (sA + TILE_ELEM);

#pragma unroll
        for (int kk = 0; kk < 4; kk++) {
            int krow = kk * 16;
            uint32_t afr[4][4];
#pragma unroll
            for (int mi = 0; mi < 4; mi++) {
                int r0 = warp_m * 64 + mi * 16;
                ldsm4(afr[mi], sA + (r0 + arow) * SPITCH + krow + acol);
            }
            uint32_t bfr[2][4];
#pragma unroll
            for (int np = 0; np < 2; np++) {
                int rn = warp_n * 32 + np * 16;
                ldsm4(bfr[np], sB + (rn + brow) * SPITCH + krow + bcol);
            }
#pragma unroll
            for (int mi = 0; mi < 4; mi++)
#pragma unroll
                for (int ni = 0; ni < 4; ni++) {
                    uint32_t b0 = bfr[ni >> 1][(ni & 1) * 2 + 0];
                    uint32_t b1 = bfr[ni >> 1][(ni & 1) * 2 + 1];
                    asm volatile(
                        "mma.sync.aligned.m16n8k16.row.col.f32.f16.f16.f32 "
                        "{%0,%1,%2,%3}, {%4,%5,%6,%7}, {%8,%9}, {%0,%1,%2,%3};"
                        : "+f"(acc[mi][ni][0]), "+f"(acc[mi][ni][1]),
                          "+f"(acc[mi][ni][2]), "+f"(acc[mi][ni][3])
                        : "r"(afr[mi][0]), "r"(afr[mi][1]),
                          "r"(afr[mi][2]), "r"(afr[mi][3]),
                          "r"(b0), "r"(b1));
                }
        }
        __syncthreads();
        buf ^= 1;
    }

    // epilogue: D frag (m = lane>>2 (+8), n = (lane&3)*2 (+1))
    int c1b = tm * 128 + warp_m * 64;
    int c2b = tn * 128 + warp_n * 32;
    int r = lane >> 2, cc = (lane & 3) * 2;
#pragma unroll
    for (int mi = 0; mi < 4; mi++) {
#pragma unroll
        for (int ni = 0; ni < 4; ni++) {
            float* d0 = g_G + ((size_t)(b * INPUT_DIM + c1b + mi * 16 + r)) * INPUT_DIM
                        + c2b + ni * 8 + cc;
            *(float2*)d0 = make_float2(acc[mi][ni][0], acc[mi][ni][1]);
            float* d1 = d0 + 8 * INPUT_DIM;
            *(float2*)d1 = make_float2(acc[mi][ni][2], acc[mi][ni][3]);
        }
    }
}

// ---------------- kernel 5: transpose G (batch-major) -> T (batch-last) ------
__global__ void transpose_kernel() {
    __shared__ float sm[8 * 32 * 33];
    int c1b = blockIdx.y * 8;
    int c2b = blockIdx.x * 32;
    if (c1b > c2b + 31) return;
    int tid = threadIdx.x;
    int lane = tid & 31, w = tid >> 5;

#pragma unroll 4
    for (int i = 0; i < 32; i++) {
        int j = i * 8 + w;
        int b = j >> 3, c1i = j & 7;
        float v = g_G[((size_t)b * INPUT_DIM + (c1b + c1i)) * INPUT_DIM + c2b + lane];
        sm[(c1i * 32 + lane) * 33 + b] = v;
    }
    __syncthreads();
#pragma unroll 4
    for (int i = 0; i < 32; i++) {
        int j = i * 8 + w;
        int c1i = j >> 5, c2i = j & 31;
        float v = sm[(c1i * 32 + c2i) * 33 + lane];
        g_T[((size_t)(c1b + c1i) * INPUT_DIM + (c2b + c2i)) * BATCH + lane] = v;
    }
}

// ---------------- kernel 6: gather pairs per bin + norm reduce ----------------
__global__ void gather_kernel() {
    __shared__ float sums[8][33];
    int warp = threadIdx.x >> 5, lane = threadIdx.x & 31;
    int bin = blockIdx.x * 8 + warp;
    int cnt = min(g_cnt[bin], CAP);
    const int2* pl = g_pairs + bin * CAP;
    float acc = 0.0f;
    int i = 0;
    for (; i + 4 <= cnt; i += 4) {
        int2 p0 = pl[i + 0];
        int2 p1 = pl[i + 1];
        int2 p2 = pl[i + 2];
        int2 p3 = pl[i + 3];
        float v0 = g_T[p0.x + lane];
        float v1 = g_T[p1.x + lane];
        float v2 = g_T[p2.x + lane];
        float v3 = g_T[p3.x + lane];
        acc = fmaf(__int_as_float(p0.y), v0, acc);
        acc = fmaf(__int_as_float(p1.y), v1, acc);
        acc = fmaf(__int_as_float(p2.y), v2, acc);
        acc = fmaf(__int_as_float(p3.y), v3, acc);
    }
    for (; i < cnt; i++) {
        int2 p = pl[i];
        acc = fmaf(__int_as_float(p.y), g_T[p.x + lane], acc);
    }
    g_Y[bin * BATCH + lane] = acc;
    sums[warp][lane] = fabsf(acc);
    __syncthreads();
    if (warp == 0) {
        float s = 0.0f;
#pragma unroll
        for (int w = 0; w < 8; w++) s += sums[w][lane];
        atomicAdd(&g_norm[lane], s);
    }
}

// ---------------- kernel 7: signed sqrt + L2 normalize (parallel) -------------
__global__ void scale_kernel(float* __restrict__ out) {
    __shared__ float sm[32][33];
    int bin0 = blockIdx.x * 32;
    int lane = threadIdx.x & 31, w = threadIdx.x >> 5;   // 8 warps

#pragma unroll
    for (int r = w; r < 32; r += 8)
        sm[r][lane] = g_Y[(bin0 + r) * BATCH + lane];
    __syncthreads();

#pragma unroll
    for (int b = w; b < 32; b += 8) {
        float inv = rsqrtf(fmaxf(g_norm[b], 1e-10f));
        float v = sm[lane][b];
        out[(size_t)b * PROJ_DIM + bin0 + lane] = copysignf(sqrtf(fabsf(v)), v) * inv;
    }
}

// ---------------- launcher ---------------------------------------------------
extern "C" void kernel_launch(void* const* d_in, const int* in_sizes, int n_in,
                              void* d_out, int out_size) {
    const float* x  = (const float*)d_in[0];   // [32,14,14,512]
    const float* M1 = (const float*)d_in[1];   // [512,8192]
    const float* M2 = (const float*)d_in[2];   // [512,8192]
    float* out = (float*)d_out;                // [32,8192]
    (void)in_sizes; (void)n_in; (void)out_size;

    void* cnt_addr; void* norm_addr;
    cudaGetSymbolAddress(&cnt_addr, g_cnt);
    cudaGetSymbolAddress(&norm_addr, g_norm);
    cudaMemsetAsync(cnt_addr, 0, PROJ_DIM * sizeof(int));
    cudaMemsetAsync(norm_addr, 0, BATCH * sizeof(float));

    // k1: extract both sketches
    extract_both_kernel<<<2 * INPUT_DIM, 256>>>(M1, M2);
    // k2: fill buckets
    fill_kernel<<<NPAIRS / 1024, 256>>>();
    // k3: fp16 split + transpose
    {
        dim3 grid(8, 4, BATCH);
        prep_split_kernel<<<grid, 256>>>(x);
    }
    // k4: tensor-core Gram (4th kernel -> profiled by ncu)
    {
        static int smem_set = 0;
        if (!smem_set) {
            cudaFuncSetAttribute(gram_hmma_kernel,
                                 cudaFuncAttributeMaxDynamicSharedMemorySize,
                                 2 * BUF_ELEM * (int)sizeof(unsigned short));
            smem_set = 1;
        }
        dim3 grid(10, BATCH);
        gram_hmma_kernel<<<grid, 256, 2 * BUF_ELEM * sizeof(unsigned short)>>>();
    }
    // k5: transpose to batch-last
    {
        dim3 grid(16, 64);
        transpose_kernel<<<grid, 256>>>();
    }
    // k6: gather + norm reduce
    gather_kernel<<<PROJ_DIM / 8, 256>>>();
    // k7: scale
    scale_kernel<<<PROJ_DIM / 32, 256>>>(out);
}